// round 10
// baseline (speedup 1.0000x reference)
#include <cuda_runtime.h>
#include <cstdint>

// Problem constants
#define B_ 16
#define K_ 49
#define T_ 256
#define H_ 512
#define D_ 512

// Output packing: (c_hat_t, alpha_t, beta_t) flattened in order
#define OUT_ALPHA (B_ * T_ * H_)              // 2097152
#define OUT_BETA  (OUT_ALPHA + B_ * T_ * K_)  // 2297856

// Scratch. Layout trick: columns [0,256) hold RAW values, columns [256,512)
// hold tanh(value). The fused kernel uses MUFU tanh on the raw half and the
// tanh-addition identity on the tanh half.
__device__ float g_cv[B_ * K_ * D_];   // V @ Wv + bv     (lower raw / upper tanh)
__device__ float g_cg[B_ * T_ * D_];   // h_t @ Wg + bg   (lower raw / upper tanh)
__device__ float g_cs[B_ * T_ * D_];   // s_t @ Ws + bs   (lower raw / upper tanh)

__device__ __forceinline__ float ex2a(float x)
{ float r; asm("ex2.approx.f32 %0, %1;" : "=f"(r) : "f"(x)); return r; }
__device__ __forceinline__ float rcpa(float x)
{ float r; asm("rcp.approx.f32 %0, %1;" : "=f"(r) : "f"(x)); return r; }

// Accurate tanh (~1e-7): 2 MUFU. Used only in the GEMM epilogue (2.3M elems).
__device__ __forceinline__ float tanh_acc(float x)
{
    float m = x * 2.8853900817779268f;   // 2*log2(e)
    float r = rcpa(ex2a(m) + 1.0f);
    return fmaf(-2.0f, r, 1.0f);
}

// ---------------------------------------------------------------------------
// Merged TF32 mma.sync GEMM: all three C[M,512] = A[M,512]@W + bias.
// Epilogue: nt<2 stores raw, nt>=2 stores tanh(value).
// ---------------------------------------------------------------------------
__global__ __launch_bounds__(256)
void gemm3_tf32_kernel(const float* __restrict__ V, const float* __restrict__ h_t,
                       const float* __restrict__ s_t,
                       const float* __restrict__ Wv, const float* __restrict__ bv,
                       const float* __restrict__ Wg, const float* __restrict__ bg,
                       const float* __restrict__ Wss, const float* __restrict__ bss)
{
    __shared__ float As[128 * 32];     // [m][k], k index xor-swizzled by 4*(m&7)
    __shared__ float Bs[32 * 136];     // [k][n], row stride 136 (pad 8)

    const int nt = blockIdx.x;         // 0..3
    int mt = blockIdx.y;               // 0..70
    const float *A, *W, *bias;
    float* C;
    int M;
    if (mt < 7)       { A = V;   W = Wv;  bias = bv;  C = g_cv; M = B_ * K_; }
    else if (mt < 39) { A = h_t; W = Wg;  bias = bg;  C = g_cg; M = B_ * T_; mt -= 7; }
    else              { A = s_t; W = Wss; bias = bss; C = g_cs; M = B_ * T_; mt -= 39; }

    const int tid  = threadIdx.x;
    const int lane = tid & 31;
    const int wid  = tid >> 5;
    const int g    = lane >> 2;
    const int tg   = lane & 3;
    const int warp_m = (wid >> 2) * 64;
    const int warp_n = (wid & 3) * 32;

    const int mbase = mt * 128;
    const int nbase = nt * 128;
    const bool do_tanh = (nt >= 2);

    float acc[4][4][4];
    #pragma unroll
    for (int i = 0; i < 4; i++)
        #pragma unroll
        for (int j = 0; j < 4; j++)
            #pragma unroll
            for (int q = 0; q < 4; q++) acc[i][j][q] = 0.f;

    const int a_m0 = tid >> 3;
    const int a_k4 = (tid & 7) * 4;
    const int w_k0 = tid >> 5;
    const int w_n4 = (tid & 31) * 4;

    float4 pa[4], pw[4];

    #pragma unroll
    for (int i = 0; i < 4; i++) {
        const int row = mbase + a_m0 + i * 32;
        pa[i] = (row < M) ? *reinterpret_cast<const float4*>(&A[(size_t)row * 512 + a_k4])
                          : make_float4(0.f, 0.f, 0.f, 0.f);
        pw[i] = *reinterpret_cast<const float4*>(&W[(size_t)(w_k0 + i * 8) * 512 + nbase + w_n4]);
    }
    #pragma unroll
    for (int i = 0; i < 4; i++) {
        const int m = a_m0 + i * 32;
        *reinterpret_cast<float4*>(&As[m * 32 + (a_k4 ^ (4 * (m & 7)))]) = pa[i];
        *reinterpret_cast<float4*>(&Bs[(w_k0 + i * 8) * 136 + w_n4]) = pw[i];
    }
    __syncthreads();

    const int sw = 4 * g;

    for (int kt = 0; kt < 512; kt += 32) {
        if (kt + 32 < 512) {
            #pragma unroll
            for (int i = 0; i < 4; i++) {
                const int row = mbase + a_m0 + i * 32;
                pa[i] = (row < M) ? *reinterpret_cast<const float4*>(&A[(size_t)row * 512 + kt + 32 + a_k4])
                                  : make_float4(0.f, 0.f, 0.f, 0.f);
                pw[i] = *reinterpret_cast<const float4*>(&W[(size_t)(kt + 32 + w_k0 + i * 8) * 512 + nbase + w_n4]);
            }
        }

        #pragma unroll
        for (int kb = 0; kb < 32; kb += 8) {
            uint32_t af[4][4], bf[4][2];
            #pragma unroll
            for (int mi = 0; mi < 4; mi++) {
                const int m0 = warp_m + mi * 16;
                const int k0 = (kb + tg) ^ sw;
                const int k1 = (kb + tg + 4) ^ sw;
                af[mi][0] = __float_as_uint(As[(m0 + g)     * 32 + k0]);
                af[mi][1] = __float_as_uint(As[(m0 + g + 8) * 32 + k0]);
                af[mi][2] = __float_as_uint(As[(m0 + g)     * 32 + k1]);
                af[mi][3] = __float_as_uint(As[(m0 + g + 8) * 32 + k1]);
            }
            #pragma unroll
            for (int ni = 0; ni < 4; ni++) {
                const int n_ = warp_n + ni * 8 + g;
                bf[ni][0] = __float_as_uint(Bs[(kb + tg)     * 136 + n_]);
                bf[ni][1] = __float_as_uint(Bs[(kb + tg + 4) * 136 + n_]);
            }
            #pragma unroll
            for (int mi = 0; mi < 4; mi++)
                #pragma unroll
                for (int ni = 0; ni < 4; ni++) {
                    asm volatile(
                        "mma.sync.aligned.m16n8k8.row.col.f32.tf32.tf32.f32 "
                        "{%0,%1,%2,%3}, {%4,%5,%6,%7}, {%8,%9}, {%0,%1,%2,%3};"
                        : "+f"(acc[mi][ni][0]), "+f"(acc[mi][ni][1]),
                          "+f"(acc[mi][ni][2]), "+f"(acc[mi][ni][3])
                        : "r"(af[mi][0]), "r"(af[mi][1]), "r"(af[mi][2]), "r"(af[mi][3]),
                          "r"(bf[ni][0]), "r"(bf[ni][1]));
                }
        }
        __syncthreads();
        if (kt + 32 < 512) {
            #pragma unroll
            for (int i = 0; i < 4; i++) {
                const int m = a_m0 + i * 32;
                *reinterpret_cast<float4*>(&As[m * 32 + (a_k4 ^ (4 * (m & 7)))]) = pa[i];
                *reinterpret_cast<float4*>(&Bs[(w_k0 + i * 8) * 136 + w_n4]) = pw[i];
            }
            __syncthreads();
        }
    }

    #pragma unroll
    for (int mi = 0; mi < 4; mi++) {
        const int r0 = mbase + warp_m + mi * 16 + g;
        const int r1 = r0 + 8;
        #pragma unroll
        for (int ni = 0; ni < 4; ni++) {
            const int c = nbase + warp_n + ni * 8 + tg * 2;
            const float2 bv2 = *reinterpret_cast<const float2*>(&bias[c]);
            float o00 = acc[mi][ni][0] + bv2.x, o01 = acc[mi][ni][1] + bv2.y;
            float o10 = acc[mi][ni][2] + bv2.x, o11 = acc[mi][ni][3] + bv2.y;
            if (do_tanh) {
                o00 = tanh_acc(o00); o01 = tanh_acc(o01);
                o10 = tanh_acc(o10); o11 = tanh_acc(o11);
            }
            if (r0 < M)
                *reinterpret_cast<float2*>(&C[(size_t)r0 * 512 + c]) = make_float2(o00, o01);
            if (r1 < M)
                *reinterpret_cast<float2*>(&C[(size_t)r1 * 512 + c]) = make_float2(o10, o11);
        }
    }
}

// Single-MUFU tanh (MUFU.TANH, rt~16). Max abs err ~5e-4.
__device__ __forceinline__ float tanha(float x)
{
    float r;
    asm("tanh.approx.f32 %0, %1;" : "=f"(r) : "f"(x));
    return r;
}

// Hybrid z-row lane partial over d = 128j + 4*lane + c:
//  j=0,1: raw halves -> MUFU.TANH path
//  j=2,3: tanh halves -> addition identity (FMA pipe + 1 batched rcp per 4)
__device__ __forceinline__ float z_row_hyb(const float* __restrict__ r,
                                           const float4 cg[2], const float4 tcg[2],
                                           const float4 wh[4])
{
    float acc = 0.f;
    // MUFU half
    #pragma unroll
    for (int j = 0; j < 2; j++) {
        float4 v = *reinterpret_cast<const float4*>(&r[j * 128]);
        acc = fmaf(tanha(v.x + cg[j].x), wh[j].x, acc);
        acc = fmaf(tanha(v.y + cg[j].y), wh[j].y, acc);
        acc = fmaf(tanha(v.z + cg[j].z), wh[j].z, acc);
        acc = fmaf(tanha(v.w + cg[j].w), wh[j].w, acc);
    }
    // identity half: tanh(a+b) = (ta+tb)/(1+ta*tb), batched reciprocal
    #pragma unroll
    for (int j = 0; j < 2; j++) {
        float4 ta = *reinterpret_cast<const float4*>(&r[(j + 2) * 128]);
        const float4 tb = tcg[j];
        float nx = ta.x + tb.x, ny = ta.y + tb.y, nz = ta.z + tb.z, nw = ta.w + tb.w;
        float dx = fmaf(ta.x, tb.x, 1.0f);
        float dy = fmaf(ta.y, tb.y, 1.0f);
        float dz = fmaf(ta.z, tb.z, 1.0f);
        float dw = fmaf(ta.w, tb.w, 1.0f);
        float t01 = dx * dy, t23 = dz * dw;
        float R   = rcpa(t01 * t23);
        float R01 = R * t23, R23 = R * t01;
        acc = fmaf(nx * (R01 * dy), wh[j + 2].x, acc);
        acc = fmaf(ny * (R01 * dx), wh[j + 2].y, acc);
        acc = fmaf(nz * (R23 * dw), wh[j + 2].z, acc);
        acc = fmaf(nw * (R23 * dz), wh[j + 2].w, acc);
    }
    return acc;
}

// ---------------------------------------------------------------------------
// Fused kernel, one CTA per (b,t): grid = B*T = 4096, 128 threads (4 warps).
// Warps split k (stride-4, 13/12/12/12). Warp 3 adds z_ext; warp 0 softmax.
// ---------------------------------------------------------------------------
__global__ __launch_bounds__(128, 8)
void fused_attn_kernel(const float* __restrict__ V, const float* __restrict__ s_t,
                       const float* __restrict__ Wh, const float* __restrict__ bh,
                       float* __restrict__ out)
{
    __shared__ __align__(16) float part[4][512];
    __shared__ float z_s[52];
    __shared__ float alpha_s[52];
    __shared__ float beta_sh;

    const int tid  = threadIdx.x;
    const int lane = tid & 31;
    const int w    = tid >> 5;
    const int bt = blockIdx.x;
    const int b  = bt >> 8;            // bt / T_

    // cg raw (j=0,1), tanh(cg) (j=2,3), Wh: register-resident.
    float4 cg[2], tcg[2], wh[4];
    {
        const float* __restrict__ cgrow = g_cg + (size_t)bt * 512 + lane * 4;
        const float* __restrict__ whrow = Wh + lane * 4;
        #pragma unroll
        for (int j = 0; j < 2; j++) {
            cg[j]  = *reinterpret_cast<const float4*>(&cgrow[j * 128]);
            tcg[j] = *reinterpret_cast<const float4*>(&cgrow[(j + 2) * 128]);
        }
        #pragma unroll
        for (int j = 0; j < 4; j++)
            wh[j] = *reinterpret_cast<const float4*>(&whrow[j * 128]);
    }
    const float bhv = bh[0];

    const float* __restrict__ cvb = g_cv + (size_t)b * (K_ * 512) + lane * 4;

    // ---- z over this warp's k-subset: k = w, w+4, w+8, ... ----
    const int n = (K_ - w + 3) >> 2;   // 13,12,12,12
    int i = 0;
    for (; i + 1 < n; i += 2) {
        const int k0 = w + 4 * i;
        const int k1 = k0 + 4;
        float a0 = z_row_hyb(cvb + (size_t)k0 * 512, cg, tcg, wh);
        float a1 = z_row_hyb(cvb + (size_t)k1 * 512, cg, tcg, wh);
        #pragma unroll
        for (int o = 16; o > 0; o >>= 1) {
            a0 += __shfl_xor_sync(0xffffffffu, a0, o);
            a1 += __shfl_xor_sync(0xffffffffu, a1, o);
        }
        if (lane == 0) { z_s[k0] = a0 + bhv; z_s[k1] = a1 + bhv; }
    }
    if (i < n) {
        const int k0 = w + 4 * i;
        float a0 = z_row_hyb(cvb + (size_t)k0 * 512, cg, tcg, wh);
        #pragma unroll
        for (int o = 16; o > 0; o >>= 1)
            a0 += __shfl_xor_sync(0xffffffffu, a0, o);
        if (lane == 0) z_s[k0] = a0 + bhv;
    }

    // ---- z_ext (warp 3): same hybrid on g_cs row ----
    if (w == 3) {
        float acc = z_row_hyb(g_cs + (size_t)bt * 512 + lane * 4, cg, tcg, wh);
        #pragma unroll
        for (int o = 16; o > 0; o >>= 1)
            acc += __shfl_xor_sync(0xffffffffu, acc, o);
        if (lane == 0) z_s[K_] = acc + bhv;
    }
    __syncthreads();

    // ---- softmaxes (warp 0): alpha over 49, beta from extended 50 ----
    if (w == 0) {
        float z0 = (lane < K_)      ? z_s[lane]      : -1e30f;
        float z1 = (lane + 32 < K_) ? z_s[lane + 32] : -1e30f;
        float ze = z_s[K_];
        float m = fmaxf(fmaxf(z0, z1), ze);
        #pragma unroll
        for (int o = 16; o > 0; o >>= 1)
            m = fmaxf(m, __shfl_xor_sync(0xffffffffu, m, o));

        float e0 = (lane < K_)      ? __expf(z0 - m) : 0.f;
        float e1 = (lane + 32 < K_) ? __expf(z1 - m) : 0.f;
        float ee = __expf(ze - m);

        float s = e0 + e1;
        #pragma unroll
        for (int o = 16; o > 0; o >>= 1)
            s += __shfl_xor_sync(0xffffffffu, s, o);
        const float beta = ee / (s + ee);
        const float inv = 1.0f / s;

        if (lane < K_) {
            float a0 = e0 * inv;
            alpha_s[lane] = a0;
            out[OUT_ALPHA + (size_t)bt * K_ + lane] = a0;
        }
        if (lane + 32 < K_) {
            float a1 = e1 * inv;
            alpha_s[lane + 32] = a1;
            out[OUT_ALPHA + (size_t)bt * K_ + lane + 32] = a1;
        }
        if (lane == 0) {
            beta_sh = beta;
            out[OUT_BETA + bt] = beta;
        }
    }
    __syncthreads();

    // ---- c_t partial over this warp's k-subset ----
    float4 cacc[4];
    #pragma unroll
    for (int j = 0; j < 4; j++) cacc[j] = make_float4(0.f, 0.f, 0.f, 0.f);

    const float* __restrict__ Vb = V + (size_t)b * (K_ * 512) + lane * 4;
    i = 0;
    for (; i + 1 < n; i += 2) {
        const int k0 = w + 4 * i;
        const int k1 = k0 + 4;
        const float a0 = alpha_s[k0];
        const float a1 = alpha_s[k1];
        const float* __restrict__ r0 = Vb + (size_t)k0 * 512;
        const float* __restrict__ r1 = Vb + (size_t)k1 * 512;
        #pragma unroll
        for (int j = 0; j < 4; j++) {
            float4 va = *reinterpret_cast<const float4*>(&r0[j * 128]);
            float4 vb = *reinterpret_cast<const float4*>(&r1[j * 128]);
            cacc[j].x = fmaf(a0, va.x, fmaf(a1, vb.x, cacc[j].x));
            cacc[j].y = fmaf(a0, va.y, fmaf(a1, vb.y, cacc[j].y));
            cacc[j].z = fmaf(a0, va.z, fmaf(a1, vb.z, cacc[j].z));
            cacc[j].w = fmaf(a0, va.w, fmaf(a1, vb.w, cacc[j].w));
        }
    }
    if (i < n) {
        const int k0 = w + 4 * i;
        const float a0 = alpha_s[k0];
        const float* __restrict__ r0 = Vb + (size_t)k0 * 512;
        #pragma unroll
        for (int j = 0; j < 4; j++) {
            float4 va = *reinterpret_cast<const float4*>(&r0[j * 128]);
            cacc[j].x = fmaf(a0, va.x, cacc[j].x);
            cacc[j].y = fmaf(a0, va.y, cacc[j].y);
            cacc[j].z = fmaf(a0, va.z, cacc[j].z);
            cacc[j].w = fmaf(a0, va.w, cacc[j].w);
        }
    }
    #pragma unroll
    for (int j = 0; j < 4; j++)
        *reinterpret_cast<float4*>(&part[w][j * 128 + lane * 4]) = cacc[j];
    __syncthreads();

    // ---- combine partials + blend: thread owns d in [4*tid, 4*tid+4) ----
    {
        const float beta = beta_sh;
        const int d = tid * 4;
        float4 p0 = *reinterpret_cast<const float4*>(&part[0][d]);
        float4 p1 = *reinterpret_cast<const float4*>(&part[1][d]);
        float4 p2 = *reinterpret_cast<const float4*>(&part[2][d]);
        float4 p3 = *reinterpret_cast<const float4*>(&part[3][d]);
        float4 c;
        c.x = (p0.x + p1.x) + (p2.x + p3.x);
        c.y = (p0.y + p1.y) + (p2.y + p3.y);
        c.z = (p0.z + p1.z) + (p2.z + p3.z);
        c.w = (p0.w + p1.w) + (p2.w + p3.w);
        float4 sv = *reinterpret_cast<const float4*>(&s_t[(size_t)bt * 512 + d]);
        float4 o;
        o.x = fmaf(beta, sv.x - c.x, c.x);
        o.y = fmaf(beta, sv.y - c.y, c.y);
        o.z = fmaf(beta, sv.z - c.z, c.z);
        o.w = fmaf(beta, sv.w - c.w, c.w);
        *reinterpret_cast<float4*>(&out[(size_t)bt * 512 + d]) = o;
    }
}

// ---------------------------------------------------------------------------
extern "C" void kernel_launch(void* const* d_in, const int* in_sizes, int n_in,
                              void* d_out, int out_size)
{
    (void)in_sizes; (void)n_in; (void)out_size;
    const float* V   = (const float*)d_in[0];
    const float* h_t = (const float*)d_in[1];
    const float* s_t = (const float*)d_in[2];
    const float* Wv  = (const float*)d_in[3];
    const float* bv  = (const float*)d_in[4];
    const float* Wg  = (const float*)d_in[5];
    const float* bg  = (const float*)d_in[6];
    const float* Ws  = (const float*)d_in[7];
    const float* bs  = (const float*)d_in[8];
    const float* Wh  = (const float*)d_in[9];
    const float* bh  = (const float*)d_in[10];
    float* out = (float*)d_out;

    gemm3_tf32_kernel<<<dim3(4, 71), 256>>>(V, h_t, s_t, Wv, bv, Wg, bg, Ws, bs);
    fused_attn_kernel<<<dim3(B_ * T_), 128>>>(V, s_t, Wh, bh, out);
}